// round 14
// baseline (speedup 1.0000x reference)
#include <cuda_runtime.h>
#include <cstdint>

#define OMEGA_W 0.9f

#define N0 2048
#define N1 1024
#define N2 512
#define N3 256

// Scratch (device globals — no allocation allowed).
__device__ float g_u0b[N0 * N0];
__device__ float g_u0c[N0 * N0];
__device__ float g_u1a[N1 * N1];
__device__ float g_u1b[N1 * N1];
__device__ float g_r1[N1 * N1];
__device__ float g_u2a[N2 * N2];
__device__ float g_u2b[N2 * N2];
__device__ float g_r2[N2 * N2];
__device__ float g_u3a[N3 * N3];
__device__ float g_u3b[N3 * N3];
__device__ float g_r3[N3 * N3];

// Software grid-barrier ticket counter (monotonic; replay-safe under graphs).
__device__ unsigned int g_l3_bar = 0;

// ---------------------------------------------------------------------------
// Checked point helpers.
// ---------------------------------------------------------------------------
__device__ __forceinline__ float jac_pt(const float* __restrict__ u,
                                        const float* __restrict__ rhs,
                                        const float* __restrict__ cx,
                                        const float* __restrict__ cy,
                                        int gy, int gx, int n, float ih2) {
    int idx = gy * n + gx;
    float um = u[idx];
    float ue = (gx + 1 < n) ? u[idx + 1] : 0.0f;
    float uw = (gx > 0) ? u[idx - 1] : 0.0f;
    float uN = (gy + 1 < n) ? u[idx + n] : 0.0f;
    float uS = (gy > 0) ? u[idx - n] : 0.0f;
    float cxe = cx[idx];
    float cxw = (gx > 0) ? cx[idx - 1] : 0.0f;
    float cyn = cy[idx];
    float cys = (gy > 0) ? cy[idx - n] : 0.0f;
    float lap = (cxe * (ue - um) - cxw * (um - uw)) * ih2 +
                (cyn * (uN - um) - cys * (um - uS)) * ih2;
    float r = rhs[idx] - (lap - um);
    float diag = -((cxe + cxw) + (cyn + cys)) * ih2 - 1.0f;
    return um + __fdividef(OMEGA_W * r, diag);
}

__device__ __forceinline__ float jac_sm(const float* __restrict__ sm,
                                        int ly, int lx, int stride,
                                        const float* __restrict__ rhs,
                                        const float* __restrict__ cx,
                                        const float* __restrict__ cy,
                                        int gy, int gx, int n, float ih2) {
    int lp = ly * stride + lx;
    float um = sm[lp];
    int idx = gy * n + gx;
    float cxe = cx[idx];
    float cxw = (gx > 0) ? cx[idx - 1] : 0.0f;
    float cyn = cy[idx];
    float cys = (gy > 0) ? cy[idx - n] : 0.0f;
    float lap = (cxe * (sm[lp + 1] - um) - cxw * (um - sm[lp - 1])) * ih2 +
                (cyn * (sm[lp + stride] - um) - cys * (um - sm[lp - stride])) * ih2;
    float r = rhs[idx] - (lap - um);
    float diag = -((cxe + cxw) + (cyn + cys)) * ih2 - 1.0f;
    return um + __fdividef(OMEGA_W * r, diag);
}

__device__ __forceinline__ float resid_sm(const float* __restrict__ sm,
                                          int ly, int lx, int stride,
                                          const float* __restrict__ rhs,
                                          const float* __restrict__ cx,
                                          const float* __restrict__ cy,
                                          int gy, int gx, int n, float ih2) {
    int lp = ly * stride + lx;
    float um = sm[lp];
    int idx = gy * n + gx;
    float cxe = cx[idx];
    float cxw = (gx > 0) ? cx[idx - 1] : 0.0f;
    float cyn = cy[idx];
    float cys = (gy > 0) ? cy[idx - n] : 0.0f;
    float lap = (cxe * (sm[lp + 1] - um) - cxw * (um - sm[lp - 1])) * ih2 +
                (cyn * (sm[lp + stride] - um) - cys * (um - sm[lp - stride])) * ih2;
    return rhs[idx] - (lap - um);
}

// ---------------------------------------------------------------------------
// Unchecked (interior) point helpers — direct flat index.
// ---------------------------------------------------------------------------
__device__ __forceinline__ float jac_pt_i(const float* __restrict__ u,
                                          const float* __restrict__ rhs,
                                          const float* __restrict__ cx,
                                          const float* __restrict__ cy,
                                          int idx, int n, float ih2) {
    float um = u[idx];
    float cxe = cx[idx], cxw = cx[idx - 1];
    float cyn = cy[idx], cys = cy[idx - n];
    float lap = (cxe * (u[idx + 1] - um) - cxw * (um - u[idx - 1])) * ih2 +
                (cyn * (u[idx + n] - um) - cys * (um - u[idx - n])) * ih2;
    float r = rhs[idx] - (lap - um);
    float diag = -((cxe + cxw) + (cyn + cys)) * ih2 - 1.0f;
    return um + __fdividef(OMEGA_W * r, diag);
}

__device__ __forceinline__ float jac_sm_i(const float* __restrict__ sm,
                                          int lp, int stride,
                                          const float* __restrict__ rhs,
                                          const float* __restrict__ cx,
                                          const float* __restrict__ cy,
                                          int idx, int n, float ih2) {
    float um = sm[lp];
    float cxe = cx[idx], cxw = cx[idx - 1];
    float cyn = cy[idx], cys = cy[idx - n];
    float lap = (cxe * (sm[lp + 1] - um) - cxw * (um - sm[lp - 1])) * ih2 +
                (cyn * (sm[lp + stride] - um) - cys * (um - sm[lp - stride])) * ih2;
    float r = rhs[idx] - (lap - um);
    float diag = -((cxe + cxw) + (cyn + cys)) * ih2 - 1.0f;
    return um + __fdividef(OMEGA_W * r, diag);
}

__device__ __forceinline__ float resid_sm_i(const float* __restrict__ sm,
                                            int lp, int stride,
                                            const float* __restrict__ rhs,
                                            const float* __restrict__ cx,
                                            const float* __restrict__ cy,
                                            int idx, int n, float ih2) {
    float um = sm[lp];
    float cxe = cx[idx], cxw = cx[idx - 1];
    float cyn = cy[idx], cys = cy[idx - n];
    float lap = (cxe * (sm[lp + 1] - um) - cxw * (um - sm[lp - 1])) * ih2 +
                (cyn * (sm[lp + stride] - um) - cys * (um - sm[lp - stride])) * ih2;
    return rhs[idx] - (lap - um);
}

// ===========================================================================
// Shared tail (phases 2+3) for jrr0/jrr2.
// ===========================================================================
template <bool IN>
__device__ __forceinline__ void jrr_tail(const float* __restrict__ s1,
                                         float* __restrict__ su,
                                         const float* __restrict__ rhs,
                                         const float* __restrict__ cx,
                                         const float* __restrict__ cy,
                                         float* __restrict__ udst,
                                         float* __restrict__ rc,
                                         int n, float ih2,
                                         int bx0, int by0, int tid) {
    const int tx = tid & 31, ty = tid >> 5;
    const int base2 = (by0 - 1) * n + (bx0 - 1);

    for (int sp = tid; sp < 18 * 66; sp += 256) {
        int py = sp / 66;
        if (IN) {
            int idx = base2 + py * (n - 66) + sp;
            int lp = sp + 2 * py + 69;   // (py+1)*68 + (px+1)
            su[sp] = jac_sm_i(s1, lp, 68, rhs, cx, cy, idx, n, ih2);
        } else {
            int px = sp - py * 66;
            int gy = by0 + py - 1, gx = bx0 + px - 1;
            float v = 0.0f;
            if ((unsigned)gy < (unsigned)n && (unsigned)gx < (unsigned)n)
                v = jac_sm(s1, py + 1, px + 1, 68, rhs, cx, cy, gy, gx, n, ih2);
            su[sp] = v;
        }
    }
    __syncthreads();

    const int gx0 = bx0 + 2 * tx, gy0 = by0 + 2 * ty;
    const int lx0 = 2 * tx + 1, ly0 = 2 * ty + 1;

    *reinterpret_cast<float2*>(&udst[gy0 * n + gx0]) =
        make_float2(su[ly0 * 66 + lx0], su[ly0 * 66 + lx0 + 1]);
    *reinterpret_cast<float2*>(&udst[(gy0 + 1) * n + gx0]) =
        make_float2(su[(ly0 + 1) * 66 + lx0], su[(ly0 + 1) * 66 + lx0 + 1]);

    float s;
    if (IN) {
        int i00 = gy0 * n + gx0;
        int l00 = ly0 * 66 + lx0;
        s = resid_sm_i(su, l00, 66, rhs, cx, cy, i00, n, ih2) +
            resid_sm_i(su, l00 + 1, 66, rhs, cx, cy, i00 + 1, n, ih2) +
            resid_sm_i(su, l00 + 66, 66, rhs, cx, cy, i00 + n, n, ih2) +
            resid_sm_i(su, l00 + 67, 66, rhs, cx, cy, i00 + n + 1, n, ih2);
    } else {
        s = resid_sm(su, ly0, lx0, 66, rhs, cx, cy, gy0, gx0, n, ih2) +
            resid_sm(su, ly0, lx0 + 1, 66, rhs, cx, cy, gy0, gx0 + 1, n, ih2) +
            resid_sm(su, ly0 + 1, lx0, 66, rhs, cx, cy, gy0 + 1, gx0, n, ih2) +
            resid_sm(su, ly0 + 1, lx0 + 1, 66, rhs, cx, cy, gy0 + 1, gx0 + 1, n, ih2);
    }
    int nc = n >> 1;
    rc[((by0 >> 1) + ty) * nc + (bx0 >> 1) + tx] = 0.25f * s;
}

// ===========================================================================
// jrr0: u==0 start.
// ===========================================================================
template <bool IN>
__device__ __forceinline__ void jrr0_body(const float* __restrict__ rhs,
                                          const float* __restrict__ cx,
                                          const float* __restrict__ cy,
                                          float* __restrict__ udst,
                                          float* __restrict__ rc,
                                          int n, float ih2,
                                          int bx0, int by0, int tid,
                                          float* s1, float* su) {
    const int base1 = (by0 - 2) * n + (bx0 - 2);
    for (int sp = tid; sp < 20 * 68; sp += 256) {
        if (IN) {
            int py = sp / 68;
            int idx = base1 + py * (n - 68) + sp;
            float cxe = cx[idx], cxw = cx[idx - 1];
            float cyn = cy[idx], cys = cy[idx - n];
            float diag = -((cxe + cxw) + (cyn + cys)) * ih2 - 1.0f;
            s1[sp] = __fdividef(OMEGA_W * rhs[idx], diag);
        } else {
            int py = sp / 68, px = sp - py * 68;
            int gy = by0 + py - 2, gx = bx0 + px - 2;
            float v = 0.0f;
            if ((unsigned)gy < (unsigned)n && (unsigned)gx < (unsigned)n) {
                int idx = gy * n + gx;
                float cxe = cx[idx];
                float cxw = (gx > 0) ? cx[idx - 1] : 0.0f;
                float cyn = cy[idx];
                float cys = (gy > 0) ? cy[idx - n] : 0.0f;
                float diag = -((cxe + cxw) + (cyn + cys)) * ih2 - 1.0f;
                v = __fdividef(OMEGA_W * rhs[idx], diag);
            }
            s1[sp] = v;
        }
    }
    __syncthreads();
    jrr_tail<IN>(s1, su, rhs, cx, cy, udst, rc, n, ih2, bx0, by0, tid);
}

__global__ __launch_bounds__(256)
void jrr0_kernel(const float* __restrict__ rhs,
                 const float* __restrict__ cx,
                 const float* __restrict__ cy,
                 float* __restrict__ udst,
                 float* __restrict__ rc, int n, float ih2) {
    __shared__ float s1[20 * 68];
    __shared__ float su[18 * 66];
    int bx0 = blockIdx.x * 64, by0 = blockIdx.y * 16;
    if (blockIdx.x > 0 && blockIdx.y > 0 &&
        blockIdx.x < gridDim.x - 1 && blockIdx.y < gridDim.y - 1)
        jrr0_body<true>(rhs, cx, cy, udst, rc, n, ih2, bx0, by0, threadIdx.x, s1, su);
    else
        jrr0_body<false>(rhs, cx, cy, udst, rc, n, ih2, bx0, by0, threadIdx.x, s1, su);
}

// ===========================================================================
// jrr2: nonzero u start.
// ===========================================================================
template <bool IN>
__device__ __forceinline__ void jrr2_body(const float* __restrict__ u,
                                          const float* __restrict__ rhs,
                                          const float* __restrict__ cx,
                                          const float* __restrict__ cy,
                                          float* __restrict__ udst,
                                          float* __restrict__ rc,
                                          int n, float ih2,
                                          int bx0, int by0, int tid,
                                          float* s1, float* su) {
    const int base1 = (by0 - 2) * n + (bx0 - 2);
    for (int sp = tid; sp < 20 * 68; sp += 256) {
        if (IN) {
            int py = sp / 68;
            int idx = base1 + py * (n - 68) + sp;
            s1[sp] = jac_pt_i(u, rhs, cx, cy, idx, n, ih2);
        } else {
            int py = sp / 68, px = sp - py * 68;
            int gy = by0 + py - 2, gx = bx0 + px - 2;
            float v = 0.0f;
            if ((unsigned)gy < (unsigned)n && (unsigned)gx < (unsigned)n)
                v = jac_pt(u, rhs, cx, cy, gy, gx, n, ih2);
            s1[sp] = v;
        }
    }
    __syncthreads();
    jrr_tail<IN>(s1, su, rhs, cx, cy, udst, rc, n, ih2, bx0, by0, tid);
}

__global__ __launch_bounds__(256)
void jrr2_kernel(const float* __restrict__ u,
                 const float* __restrict__ rhs,
                 const float* __restrict__ cx,
                 const float* __restrict__ cy,
                 float* __restrict__ udst,
                 float* __restrict__ rc, int n, float ih2) {
    __shared__ float s1[20 * 68];
    __shared__ float su[18 * 66];
    int bx0 = blockIdx.x * 64, by0 = blockIdx.y * 16;
    if (blockIdx.x > 0 && blockIdx.y > 0 &&
        blockIdx.x < gridDim.x - 1 && blockIdx.y < gridDim.y - 1)
        jrr2_body<true>(u, rhs, cx, cy, udst, rc, n, ih2, bx0, by0, threadIdx.x, s1, su);
    else
        jrr2_body<false>(u, rhs, cx, cy, udst, rc, n, ih2, bx0, by0, threadIdx.x, s1, su);
}

// ===========================================================================
// pjj: {u += prolong(e)} + two Jacobi sweeps.
// ===========================================================================
template <bool IN>
__device__ __forceinline__ void pjj_body(const float* __restrict__ u,
                                         const float* __restrict__ e,
                                         const float* __restrict__ rhs,
                                         const float* __restrict__ cx,
                                         const float* __restrict__ cy,
                                         float* __restrict__ udst,
                                         int n, float ih2,
                                         int bx0, int by0, int tid,
                                         float* s1, float* su) {
    const int tx = tid & 31, ty = tid >> 5;
    const int ncc = n >> 1;
    const int base1 = (by0 - 2) * n + (bx0 - 2);
    const int jb = (by0 - 2) >> 1;
    const int ib = (bx0 - 2) >> 1;

    for (int sp = tid; sp < 20 * 68; sp += 256) {
        int py = sp / 68, px = sp - py * 68;
        if (IN) {
            int idx = base1 + py * (n - 68) + sp;
            int jc = jb + (py >> 1);
            int sj = (py & 1) ? 1 : -1;
            int ic = ib + (px >> 1);
            int si = (px & 1) ? 1 : -1;
            const float* er = e + jc * ncc;
            const float* erj = e + (jc + sj) * ncc;
            float w = 9.0f * er[ic] + 3.0f * er[ic + si] +
                      3.0f * erj[ic] + erj[ic + si];
            s1[sp] = u[idx] + w * 0.0625f;
        } else {
            int gy = by0 + py - 2, gx = bx0 + px - 2;
            float v = 0.0f;
            if ((unsigned)gy < (unsigned)n && (unsigned)gx < (unsigned)n) {
                int jc = gy >> 1, dj = gy & 1;
                int ic = gx >> 1, di = gx & 1;
                int sj = dj ? 1 : -1;
                int si = di ? 1 : -1;
                bool bi = ((unsigned)(ic + si) < (unsigned)ncc);
                bool bj = ((unsigned)(jc + sj) < (unsigned)ncc);
                float vc = e[jc * ncc + ic];
                float vsi = bi ? e[jc * ncc + ic + si] : 0.0f;
                float vsj = bj ? e[(jc + sj) * ncc + ic] : 0.0f;
                float vd = (bi && bj) ? e[(jc + sj) * ncc + ic + si] : 0.0f;
                float den = 9.0f + 3.0f * (bi ? 1.0f : 0.0f) +
                            3.0f * (bj ? 1.0f : 0.0f) + ((bi && bj) ? 1.0f : 0.0f);
                v = u[gy * n + gx] +
                    __fdividef(9.0f * vc + 3.0f * vsi + 3.0f * vsj + vd, den);
            }
            s1[sp] = v;
        }
    }
    __syncthreads();

    const int base2 = (by0 - 1) * n + (bx0 - 1);
    for (int sp = tid; sp < 18 * 66; sp += 256) {
        int py = sp / 66;
        if (IN) {
            int idx = base2 + py * (n - 66) + sp;
            int lp = sp + 2 * py + 69;
            su[sp] = jac_sm_i(s1, lp, 68, rhs, cx, cy, idx, n, ih2);
        } else {
            int px = sp - py * 66;
            int gy = by0 + py - 1, gx = bx0 + px - 1;
            float v = 0.0f;
            if ((unsigned)gy < (unsigned)n && (unsigned)gx < (unsigned)n)
                v = jac_sm(s1, py + 1, px + 1, 68, rhs, cx, cy, gy, gx, n, ih2);
            su[sp] = v;
        }
    }
    __syncthreads();

    const int gx0 = bx0 + 2 * tx, gy0 = by0 + 2 * ty;
    const int lx0 = 2 * tx + 1, ly0 = 2 * ty + 1;
    float o00, o01, o10, o11;
    if (IN) {
        int i00 = gy0 * n + gx0;
        int l00 = ly0 * 66 + lx0;
        o00 = jac_sm_i(su, l00, 66, rhs, cx, cy, i00, n, ih2);
        o01 = jac_sm_i(su, l00 + 1, 66, rhs, cx, cy, i00 + 1, n, ih2);
        o10 = jac_sm_i(su, l00 + 66, 66, rhs, cx, cy, i00 + n, n, ih2);
        o11 = jac_sm_i(su, l00 + 67, 66, rhs, cx, cy, i00 + n + 1, n, ih2);
    } else {
        o00 = jac_sm(su, ly0, lx0, 66, rhs, cx, cy, gy0, gx0, n, ih2);
        o01 = jac_sm(su, ly0, lx0 + 1, 66, rhs, cx, cy, gy0, gx0 + 1, n, ih2);
        o10 = jac_sm(su, ly0 + 1, lx0, 66, rhs, cx, cy, gy0 + 1, gx0, n, ih2);
        o11 = jac_sm(su, ly0 + 1, lx0 + 1, 66, rhs, cx, cy, gy0 + 1, gx0 + 1, n, ih2);
    }
    *reinterpret_cast<float2*>(&udst[gy0 * n + gx0]) = make_float2(o00, o01);
    *reinterpret_cast<float2*>(&udst[(gy0 + 1) * n + gx0]) = make_float2(o10, o11);
}

__global__ __launch_bounds__(256)
void pjj_kernel(const float* __restrict__ u,
                const float* __restrict__ e,
                const float* __restrict__ rhs,
                const float* __restrict__ cx,
                const float* __restrict__ cy,
                float* __restrict__ udst, int n, float ih2) {
    __shared__ float s1[20 * 68];
    __shared__ float su[18 * 66];
    int bx0 = blockIdx.x * 64, by0 = blockIdx.y * 16;
    if (blockIdx.x > 0 && blockIdx.y > 0 &&
        blockIdx.x < gridDim.x - 1 && blockIdx.y < gridDim.y - 1)
        pjj_body<true>(u, e, rhs, cx, cy, udst, n, ih2, bx0, by0, threadIdx.x, s1, su);
    else
        pjj_body<false>(u, e, rhs, cx, cy, udst, n, ih2, bx0, by0, threadIdx.x, s1, su);
}

// ===========================================================================
// l3_one (verified ~15us): all 22 coarsest sweeps in ONE launch.
// 128 CTAs (8x16), 512 threads, owned 32x16, halo 11; coeffs in registers;
// SMEM ping-pong; software grid barrier + halo exchange at sweep 11.
// ===========================================================================
#define L3S 56

__global__ __launch_bounds__(512)
void l3_one_kernel(const float* __restrict__ r3,
                   const float* __restrict__ cx3,
                   const float* __restrict__ cy3,
                   float* __restrict__ umid,
                   float* __restrict__ uout) {
    __shared__ float ua[38 * L3S], ub[38 * L3S];
    const int tid = threadIdx.x;
    const int gx0 = blockIdx.x * 32 - 11;
    const int gy0 = blockIdx.y * 16 - 11;
    const float ih2 = 0.015625f;

    int pidx[4];
    float cae[4], caw[4], can[4], cas[4], cb[4], cu[4];
#pragma unroll
    for (int i = 0; i < 4; ++i) {
        int q = tid + 512 * i;
        pidx[i] = -1;
        cae[i] = caw[i] = can[i] = cas[i] = cb[i] = cu[i] = 0.0f;
        if (q < 36 * 52) {
            int py = q / 52 + 1, px = q % 52 + 1;
            pidx[i] = py * L3S + px;
            int gy = gy0 + py, gx = gx0 + px;
            if ((unsigned)gy < (unsigned)N3 && (unsigned)gx < (unsigned)N3) {
                int idx = gy * N3 + gx;
                float cxe = cx3[idx];
                float cxw = (gx > 0) ? cx3[idx - 1] : 0.0f;
                float cyn = cy3[idx];
                float cys = (gy > 0) ? cy3[idx - N3] : 0.0f;
                float wv = __fdividef(OMEGA_W,
                                      -((cxe + cxw) + (cyn + cys)) * ih2 - 1.0f);
                float wi = wv * ih2;
                cae[i] = wi * cxe; caw[i] = wi * cxw;
                can[i] = wi * cyn; cas[i] = wi * cys;
                cb[i] = wv * r3[idx];
            }
        }
    }

    for (int sp = tid; sp < 38 * L3S; sp += 512) { ua[sp] = 0.0f; ub[sp] = 0.0f; }
    __syncthreads();

    float* src = ua;
    float* dst = ub;
#pragma unroll 1
    for (int k = 0; k < 11; ++k) {
#pragma unroll
        for (int i = 0; i < 4; ++i) {
            int p = pidx[i];
            if (p >= 0) {
                float v = (1.0f - OMEGA_W) * cu[i] + cb[i] -
                          (cae[i] * src[p + 1] + caw[i] * src[p - 1] +
                           can[i] * src[p + L3S] + cas[i] * src[p - L3S]);
                dst[p] = v;
                cu[i] = v;
            }
        }
        __syncthreads();
        float* t = src; src = dst; dst = t;
    }

    {
        int py = 11 + (tid >> 5), px = 11 + (tid & 31);
        umid[(gy0 + py) * N3 + (gx0 + px)] = src[py * L3S + px];
    }
    __threadfence();
    __syncthreads();
    if (tid == 0) {
        unsigned ticket = atomicAdd(&g_l3_bar, 1u);
        unsigned target = (ticket / 128u + 1u) * 128u;
        while (*(volatile unsigned*)&g_l3_bar < target) __nanosleep(128);
    }
    __syncthreads();

    for (int sp = tid; sp < 38 * 54; sp += 512) {
        int py = sp / 54, px = sp % 54;
        int p = py * L3S + px;
        int gy = gy0 + py, gx = gx0 + px;
        float v = 0.0f;
        if ((unsigned)gy < (unsigned)N3 && (unsigned)gx < (unsigned)N3)
            v = umid[gy * N3 + gx];
        ua[p] = v; ub[p] = v;
    }
    __syncthreads();
#pragma unroll
    for (int i = 0; i < 4; ++i)
        if (pidx[i] >= 0) cu[i] = ua[pidx[i]];

    src = ua; dst = ub;
#pragma unroll 1
    for (int k = 0; k < 11; ++k) {
#pragma unroll
        for (int i = 0; i < 4; ++i) {
            int p = pidx[i];
            if (p >= 0) {
                float v = (1.0f - OMEGA_W) * cu[i] + cb[i] -
                          (cae[i] * src[p + 1] + caw[i] * src[p - 1] +
                           can[i] * src[p + L3S] + cas[i] * src[p - L3S]);
                dst[p] = v;
                cu[i] = v;
            }
        }
        __syncthreads();
        float* t = src; src = dst; dst = t;
    }

    {
        int py = 11 + (tid >> 5), px = 11 + (tid & 31);
        uout[(gy0 + py) * N3 + (gx0 + px)] = src[py * L3S + px];
    }
}

// ---------------------------------------------------------------------------
// Host driver: 14 launches.
// ---------------------------------------------------------------------------
extern "C" void kernel_launch(void* const* d_in, const int* in_sizes, int n_in,
                              void* d_out, int out_size) {
    const float* cx[4];
    const float* cy[4];
    const float* rhs;
    if (in_sizes[2] == in_sizes[0]) {
        for (int l = 0; l < 4; ++l) {
            cx[l] = (const float*)d_in[3 * l + 1];
            cy[l] = (const float*)d_in[3 * l + 2];
        }
        rhs = (const float*)d_in[12];
    } else {
        rhs = (const float*)d_in[0];
        for (int l = 0; l < 4; ++l) {
            cx[l] = (const float*)d_in[5 + l];
            cy[l] = (const float*)d_in[9 + l];
        }
    }

    float* uOUT = (float*)d_out;
    float *uB, *uC;
    float *u1a, *u1b, *r1;
    float *u2a, *u2b, *r2;
    float *u3a, *u3b, *r3;
    cudaGetSymbolAddress((void**)&uB, g_u0b);
    cudaGetSymbolAddress((void**)&uC, g_u0c);
    cudaGetSymbolAddress((void**)&u1a, g_u1a);
    cudaGetSymbolAddress((void**)&u1b, g_u1b);
    cudaGetSymbolAddress((void**)&r1, g_r1);
    cudaGetSymbolAddress((void**)&u2a, g_u2a);
    cudaGetSymbolAddress((void**)&u2b, g_u2b);
    cudaGetSymbolAddress((void**)&r2, g_r2);
    cudaGetSymbolAddress((void**)&u3a, g_u3a);
    cudaGetSymbolAddress((void**)&u3b, g_u3b);
    cudaGetSymbolAddress((void**)&r3, g_r3);

    const float ih2_0 = 1.0f, ih2_1 = 0.25f, ih2_2 = 0.0625f;

    dim3 t0(N0 / 64, N0 / 16);
    dim3 t1(N1 / 64, N1 / 16);
    dim3 t2(N2 / 64, N2 / 16);
    dim3 g3(8, 16);

    for (int cyc = 0; cyc < 2; ++cyc) {
        // ----- level 0: pre-smooth (2) + residual + restrict -> r1; u -> uB
        if (cyc == 0) {
            jrr0_kernel<<<t0, 256>>>(rhs, cx[0], cy[0], uB, r1, N0, ih2_0);
        } else {
            jrr2_kernel<<<t0, 256>>>(uC, rhs, cx[0], cy[0], uB, r1, N0, ih2_0);
        }

        // ----- level 1: pre (from zero) + residual + restrict -> r2
        jrr0_kernel<<<t1, 256>>>(r1, cx[1], cy[1], u1a, r2, N1, ih2_1);

        // ----- level 2: pre (from zero) + residual + restrict -> r3
        jrr0_kernel<<<t2, 256>>>(r2, cx[2], cy[2], u2a, r3, N2, ih2_2);

        // ----- level 3: all 22 sweeps in ONE launch
        l3_one_kernel<<<g3, 512>>>(r3, cx[3], cy[3], u3a, u3b);

        // ----- level 2: correct + post (2) -> u2b
        pjj_kernel<<<t2, 256>>>(u2a, u3b, r2, cx[2], cy[2], u2b, N2, ih2_2);

        // ----- level 1: correct + post (2) -> u1b
        pjj_kernel<<<t1, 256>>>(u1a, u2b, r1, cx[1], cy[1], u1b, N1, ih2_1);

        // ----- level 0: correct + post (2)
        if (cyc == 0) {
            pjj_kernel<<<t0, 256>>>(uB, u1b, rhs, cx[0], cy[0], uC, N0, ih2_0);
        } else {
            pjj_kernel<<<t0, 256>>>(uB, u1b, rhs, cx[0], cy[0], uOUT, N0, ih2_0);
        }
    }
}

// round 15
// speedup vs baseline: 1.4805x; 1.4805x over previous
#include <cuda_runtime.h>
#include <cstdint>

#define OMEGA_W 0.9f

#define N0 2048
#define N1 1024
#define N2 512
#define N3 256

// Scratch (device globals — no allocation allowed).
__device__ float g_u0b[N0 * N0];
__device__ float g_u0c[N0 * N0];
__device__ float g_u1a[N1 * N1];
__device__ float g_u1b[N1 * N1];
__device__ float g_r1[N1 * N1];
__device__ float g_u2a[N2 * N2];
__device__ float g_u2b[N2 * N2];
__device__ float g_r2[N2 * N2];
__device__ float g_u3a[N3 * N3];
__device__ float g_u3b[N3 * N3];
__device__ float g_r3[N3 * N3];

// Software grid-barrier ticket counter (monotonic; replay-safe under graphs).
__device__ unsigned int g_l3_bar = 0;

// ---------------------------------------------------------------------------
// Checked point helpers.
// ---------------------------------------------------------------------------
__device__ __forceinline__ float jac_pt(const float* __restrict__ u,
                                        const float* __restrict__ rhs,
                                        const float* __restrict__ cx,
                                        const float* __restrict__ cy,
                                        int gy, int gx, int n, float ih2) {
    int idx = gy * n + gx;
    float um = u[idx];
    float ue = (gx + 1 < n) ? u[idx + 1] : 0.0f;
    float uw = (gx > 0) ? u[idx - 1] : 0.0f;
    float uN = (gy + 1 < n) ? u[idx + n] : 0.0f;
    float uS = (gy > 0) ? u[idx - n] : 0.0f;
    float cxe = cx[idx];
    float cxw = (gx > 0) ? cx[idx - 1] : 0.0f;
    float cyn = cy[idx];
    float cys = (gy > 0) ? cy[idx - n] : 0.0f;
    float lap = (cxe * (ue - um) - cxw * (um - uw)) * ih2 +
                (cyn * (uN - um) - cys * (um - uS)) * ih2;
    float r = rhs[idx] - (lap - um);
    float diag = -((cxe + cxw) + (cyn + cys)) * ih2 - 1.0f;
    return um + __fdividef(OMEGA_W * r, diag);
}

__device__ __forceinline__ float jac_sm(const float* __restrict__ sm,
                                        int ly, int lx, int stride,
                                        const float* __restrict__ rhs,
                                        const float* __restrict__ cx,
                                        const float* __restrict__ cy,
                                        int gy, int gx, int n, float ih2) {
    int lp = ly * stride + lx;
    float um = sm[lp];
    int idx = gy * n + gx;
    float cxe = cx[idx];
    float cxw = (gx > 0) ? cx[idx - 1] : 0.0f;
    float cyn = cy[idx];
    float cys = (gy > 0) ? cy[idx - n] : 0.0f;
    float lap = (cxe * (sm[lp + 1] - um) - cxw * (um - sm[lp - 1])) * ih2 +
                (cyn * (sm[lp + stride] - um) - cys * (um - sm[lp - stride])) * ih2;
    float r = rhs[idx] - (lap - um);
    float diag = -((cxe + cxw) + (cyn + cys)) * ih2 - 1.0f;
    return um + __fdividef(OMEGA_W * r, diag);
}

__device__ __forceinline__ float resid_sm(const float* __restrict__ sm,
                                          int ly, int lx, int stride,
                                          const float* __restrict__ rhs,
                                          const float* __restrict__ cx,
                                          const float* __restrict__ cy,
                                          int gy, int gx, int n, float ih2) {
    int lp = ly * stride + lx;
    float um = sm[lp];
    int idx = gy * n + gx;
    float cxe = cx[idx];
    float cxw = (gx > 0) ? cx[idx - 1] : 0.0f;
    float cyn = cy[idx];
    float cys = (gy > 0) ? cy[idx - n] : 0.0f;
    float lap = (cxe * (sm[lp + 1] - um) - cxw * (um - sm[lp - 1])) * ih2 +
                (cyn * (sm[lp + stride] - um) - cys * (um - sm[lp - stride])) * ih2;
    return rhs[idx] - (lap - um);
}

// ---------------------------------------------------------------------------
// Unchecked (interior) point helpers — direct flat index.
// ---------------------------------------------------------------------------
__device__ __forceinline__ float jac_pt_i(const float* __restrict__ u,
                                          const float* __restrict__ rhs,
                                          const float* __restrict__ cx,
                                          const float* __restrict__ cy,
                                          int idx, int n, float ih2) {
    float um = u[idx];
    float cxe = cx[idx], cxw = cx[idx - 1];
    float cyn = cy[idx], cys = cy[idx - n];
    float lap = (cxe * (u[idx + 1] - um) - cxw * (um - u[idx - 1])) * ih2 +
                (cyn * (u[idx + n] - um) - cys * (um - u[idx - n])) * ih2;
    float r = rhs[idx] - (lap - um);
    float diag = -((cxe + cxw) + (cyn + cys)) * ih2 - 1.0f;
    return um + __fdividef(OMEGA_W * r, diag);
}

__device__ __forceinline__ float jac_sm_i(const float* __restrict__ sm,
                                          int lp, int stride,
                                          const float* __restrict__ rhs,
                                          const float* __restrict__ cx,
                                          const float* __restrict__ cy,
                                          int idx, int n, float ih2) {
    float um = sm[lp];
    float cxe = cx[idx], cxw = cx[idx - 1];
    float cyn = cy[idx], cys = cy[idx - n];
    float lap = (cxe * (sm[lp + 1] - um) - cxw * (um - sm[lp - 1])) * ih2 +
                (cyn * (sm[lp + stride] - um) - cys * (um - sm[lp - stride])) * ih2;
    float r = rhs[idx] - (lap - um);
    float diag = -((cxe + cxw) + (cyn + cys)) * ih2 - 1.0f;
    return um + __fdividef(OMEGA_W * r, diag);
}

__device__ __forceinline__ float resid_sm_i(const float* __restrict__ sm,
                                            int lp, int stride,
                                            const float* __restrict__ rhs,
                                            const float* __restrict__ cx,
                                            const float* __restrict__ cy,
                                            int idx, int n, float ih2) {
    float um = sm[lp];
    float cxe = cx[idx], cxw = cx[idx - 1];
    float cyn = cy[idx], cys = cy[idx - n];
    float lap = (cxe * (sm[lp + 1] - um) - cxw * (um - sm[lp - 1])) * ih2 +
                (cyn * (sm[lp + stride] - um) - cys * (um - sm[lp - stride])) * ih2;
    return rhs[idx] - (lap - um);
}

// ===========================================================================
// Shared tail (phases 2+3) for jrr0/jrr2.
// ===========================================================================
template <bool IN>
__device__ __forceinline__ void jrr_tail(const float* __restrict__ s1,
                                         float* __restrict__ su,
                                         const float* __restrict__ rhs,
                                         const float* __restrict__ cx,
                                         const float* __restrict__ cy,
                                         float* __restrict__ udst,
                                         float* __restrict__ rc,
                                         int n, float ih2,
                                         int bx0, int by0, int tid) {
    const int tx = tid & 31, ty = tid >> 5;
    const int base2 = (by0 - 1) * n + (bx0 - 1);

    for (int sp = tid; sp < 18 * 66; sp += 256) {
        int py = sp / 66;
        if (IN) {
            int idx = base2 + py * (n - 66) + sp;
            int lp = sp + 2 * py + 69;   // (py+1)*68 + (px+1)
            su[sp] = jac_sm_i(s1, lp, 68, rhs, cx, cy, idx, n, ih2);
        } else {
            int px = sp - py * 66;
            int gy = by0 + py - 1, gx = bx0 + px - 1;
            float v = 0.0f;
            if ((unsigned)gy < (unsigned)n && (unsigned)gx < (unsigned)n)
                v = jac_sm(s1, py + 1, px + 1, 68, rhs, cx, cy, gy, gx, n, ih2);
            su[sp] = v;
        }
    }
    __syncthreads();

    const int gx0 = bx0 + 2 * tx, gy0 = by0 + 2 * ty;
    const int lx0 = 2 * tx + 1, ly0 = 2 * ty + 1;

    *reinterpret_cast<float2*>(&udst[gy0 * n + gx0]) =
        make_float2(su[ly0 * 66 + lx0], su[ly0 * 66 + lx0 + 1]);
    *reinterpret_cast<float2*>(&udst[(gy0 + 1) * n + gx0]) =
        make_float2(su[(ly0 + 1) * 66 + lx0], su[(ly0 + 1) * 66 + lx0 + 1]);

    float s;
    if (IN) {
        int i00 = gy0 * n + gx0;
        int l00 = ly0 * 66 + lx0;
        s = resid_sm_i(su, l00, 66, rhs, cx, cy, i00, n, ih2) +
            resid_sm_i(su, l00 + 1, 66, rhs, cx, cy, i00 + 1, n, ih2) +
            resid_sm_i(su, l00 + 66, 66, rhs, cx, cy, i00 + n, n, ih2) +
            resid_sm_i(su, l00 + 67, 66, rhs, cx, cy, i00 + n + 1, n, ih2);
    } else {
        s = resid_sm(su, ly0, lx0, 66, rhs, cx, cy, gy0, gx0, n, ih2) +
            resid_sm(su, ly0, lx0 + 1, 66, rhs, cx, cy, gy0, gx0 + 1, n, ih2) +
            resid_sm(su, ly0 + 1, lx0, 66, rhs, cx, cy, gy0 + 1, gx0, n, ih2) +
            resid_sm(su, ly0 + 1, lx0 + 1, 66, rhs, cx, cy, gy0 + 1, gx0 + 1, n, ih2);
    }
    int nc = n >> 1;
    rc[((by0 >> 1) + ty) * nc + (bx0 >> 1) + tx] = 0.25f * s;
}

// ===========================================================================
// jrr0: u==0 start.
// ===========================================================================
template <bool IN>
__device__ __forceinline__ void jrr0_body(const float* __restrict__ rhs,
                                          const float* __restrict__ cx,
                                          const float* __restrict__ cy,
                                          float* __restrict__ udst,
                                          float* __restrict__ rc,
                                          int n, float ih2,
                                          int bx0, int by0, int tid,
                                          float* s1, float* su) {
    const int base1 = (by0 - 2) * n + (bx0 - 2);
    for (int sp = tid; sp < 20 * 68; sp += 256) {
        if (IN) {
            int py = sp / 68;
            int idx = base1 + py * (n - 68) + sp;
            float cxe = cx[idx], cxw = cx[idx - 1];
            float cyn = cy[idx], cys = cy[idx - n];
            float diag = -((cxe + cxw) + (cyn + cys)) * ih2 - 1.0f;
            s1[sp] = __fdividef(OMEGA_W * rhs[idx], diag);
        } else {
            int py = sp / 68, px = sp - py * 68;
            int gy = by0 + py - 2, gx = bx0 + px - 2;
            float v = 0.0f;
            if ((unsigned)gy < (unsigned)n && (unsigned)gx < (unsigned)n) {
                int idx = gy * n + gx;
                float cxe = cx[idx];
                float cxw = (gx > 0) ? cx[idx - 1] : 0.0f;
                float cyn = cy[idx];
                float cys = (gy > 0) ? cy[idx - n] : 0.0f;
                float diag = -((cxe + cxw) + (cyn + cys)) * ih2 - 1.0f;
                v = __fdividef(OMEGA_W * rhs[idx], diag);
            }
            s1[sp] = v;
        }
    }
    __syncthreads();
    jrr_tail<IN>(s1, su, rhs, cx, cy, udst, rc, n, ih2, bx0, by0, tid);
}

__global__ __launch_bounds__(256)
void jrr0_kernel(const float* __restrict__ rhs,
                 const float* __restrict__ cx,
                 const float* __restrict__ cy,
                 float* __restrict__ udst,
                 float* __restrict__ rc, int n, float ih2) {
    __shared__ float s1[20 * 68];
    __shared__ float su[18 * 66];
    int bx0 = blockIdx.x * 64, by0 = blockIdx.y * 16;
    if (blockIdx.x > 0 && blockIdx.y > 0 &&
        blockIdx.x < gridDim.x - 1 && blockIdx.y < gridDim.y - 1)
        jrr0_body<true>(rhs, cx, cy, udst, rc, n, ih2, bx0, by0, threadIdx.x, s1, su);
    else
        jrr0_body<false>(rhs, cx, cy, udst, rc, n, ih2, bx0, by0, threadIdx.x, s1, su);
}

// ===========================================================================
// jrr2: nonzero u start.
// ===========================================================================
template <bool IN>
__device__ __forceinline__ void jrr2_body(const float* __restrict__ u,
                                          const float* __restrict__ rhs,
                                          const float* __restrict__ cx,
                                          const float* __restrict__ cy,
                                          float* __restrict__ udst,
                                          float* __restrict__ rc,
                                          int n, float ih2,
                                          int bx0, int by0, int tid,
                                          float* s1, float* su) {
    const int base1 = (by0 - 2) * n + (bx0 - 2);
    for (int sp = tid; sp < 20 * 68; sp += 256) {
        if (IN) {
            int py = sp / 68;
            int idx = base1 + py * (n - 68) + sp;
            s1[sp] = jac_pt_i(u, rhs, cx, cy, idx, n, ih2);
        } else {
            int py = sp / 68, px = sp - py * 68;
            int gy = by0 + py - 2, gx = bx0 + px - 2;
            float v = 0.0f;
            if ((unsigned)gy < (unsigned)n && (unsigned)gx < (unsigned)n)
                v = jac_pt(u, rhs, cx, cy, gy, gx, n, ih2);
            s1[sp] = v;
        }
    }
    __syncthreads();
    jrr_tail<IN>(s1, su, rhs, cx, cy, udst, rc, n, ih2, bx0, by0, tid);
}

__global__ __launch_bounds__(256)
void jrr2_kernel(const float* __restrict__ u,
                 const float* __restrict__ rhs,
                 const float* __restrict__ cx,
                 const float* __restrict__ cy,
                 float* __restrict__ udst,
                 float* __restrict__ rc, int n, float ih2) {
    __shared__ float s1[20 * 68];
    __shared__ float su[18 * 66];
    int bx0 = blockIdx.x * 64, by0 = blockIdx.y * 16;
    if (blockIdx.x > 0 && blockIdx.y > 0 &&
        blockIdx.x < gridDim.x - 1 && blockIdx.y < gridDim.y - 1)
        jrr2_body<true>(u, rhs, cx, cy, udst, rc, n, ih2, bx0, by0, threadIdx.x, s1, su);
    else
        jrr2_body<false>(u, rhs, cx, cy, udst, rc, n, ih2, bx0, by0, threadIdx.x, s1, su);
}

// ===========================================================================
// pjj: {u += prolong(e)} + two Jacobi sweeps.
// ===========================================================================
template <bool IN>
__device__ __forceinline__ void pjj_body(const float* __restrict__ u,
                                         const float* __restrict__ e,
                                         const float* __restrict__ rhs,
                                         const float* __restrict__ cx,
                                         const float* __restrict__ cy,
                                         float* __restrict__ udst,
                                         int n, float ih2,
                                         int bx0, int by0, int tid,
                                         float* s1, float* su) {
    const int tx = tid & 31, ty = tid >> 5;
    const int ncc = n >> 1;
    const int base1 = (by0 - 2) * n + (bx0 - 2);
    const int jb = (by0 - 2) >> 1;
    const int ib = (bx0 - 2) >> 1;

    for (int sp = tid; sp < 20 * 68; sp += 256) {
        int py = sp / 68, px = sp - py * 68;
        if (IN) {
            int idx = base1 + py * (n - 68) + sp;
            int jc = jb + (py >> 1);
            int sj = (py & 1) ? 1 : -1;
            int ic = ib + (px >> 1);
            int si = (px & 1) ? 1 : -1;
            const float* er = e + jc * ncc;
            const float* erj = e + (jc + sj) * ncc;
            float w = 9.0f * er[ic] + 3.0f * er[ic + si] +
                      3.0f * erj[ic] + erj[ic + si];
            s1[sp] = u[idx] + w * 0.0625f;
        } else {
            int gy = by0 + py - 2, gx = bx0 + px - 2;
            float v = 0.0f;
            if ((unsigned)gy < (unsigned)n && (unsigned)gx < (unsigned)n) {
                int jc = gy >> 1, dj = gy & 1;
                int ic = gx >> 1, di = gx & 1;
                int sj = dj ? 1 : -1;
                int si = di ? 1 : -1;
                bool bi = ((unsigned)(ic + si) < (unsigned)ncc);
                bool bj = ((unsigned)(jc + sj) < (unsigned)ncc);
                float vc = e[jc * ncc + ic];
                float vsi = bi ? e[jc * ncc + ic + si] : 0.0f;
                float vsj = bj ? e[(jc + sj) * ncc + ic] : 0.0f;
                float vd = (bi && bj) ? e[(jc + sj) * ncc + ic + si] : 0.0f;
                float den = 9.0f + 3.0f * (bi ? 1.0f : 0.0f) +
                            3.0f * (bj ? 1.0f : 0.0f) + ((bi && bj) ? 1.0f : 0.0f);
                v = u[gy * n + gx] +
                    __fdividef(9.0f * vc + 3.0f * vsi + 3.0f * vsj + vd, den);
            }
            s1[sp] = v;
        }
    }
    __syncthreads();

    const int base2 = (by0 - 1) * n + (bx0 - 1);
    for (int sp = tid; sp < 18 * 66; sp += 256) {
        int py = sp / 66;
        if (IN) {
            int idx = base2 + py * (n - 66) + sp;
            int lp = sp + 2 * py + 69;
            su[sp] = jac_sm_i(s1, lp, 68, rhs, cx, cy, idx, n, ih2);
        } else {
            int px = sp - py * 66;
            int gy = by0 + py - 1, gx = bx0 + px - 1;
            float v = 0.0f;
            if ((unsigned)gy < (unsigned)n && (unsigned)gx < (unsigned)n)
                v = jac_sm(s1, py + 1, px + 1, 68, rhs, cx, cy, gy, gx, n, ih2);
            su[sp] = v;
        }
    }
    __syncthreads();

    const int gx0 = bx0 + 2 * tx, gy0 = by0 + 2 * ty;
    const int lx0 = 2 * tx + 1, ly0 = 2 * ty + 1;
    float o00, o01, o10, o11;
    if (IN) {
        int i00 = gy0 * n + gx0;
        int l00 = ly0 * 66 + lx0;
        o00 = jac_sm_i(su, l00, 66, rhs, cx, cy, i00, n, ih2);
        o01 = jac_sm_i(su, l00 + 1, 66, rhs, cx, cy, i00 + 1, n, ih2);
        o10 = jac_sm_i(su, l00 + 66, 66, rhs, cx, cy, i00 + n, n, ih2);
        o11 = jac_sm_i(su, l00 + 67, 66, rhs, cx, cy, i00 + n + 1, n, ih2);
    } else {
        o00 = jac_sm(su, ly0, lx0, 66, rhs, cx, cy, gy0, gx0, n, ih2);
        o01 = jac_sm(su, ly0, lx0 + 1, 66, rhs, cx, cy, gy0, gx0 + 1, n, ih2);
        o10 = jac_sm(su, ly0 + 1, lx0, 66, rhs, cx, cy, gy0 + 1, gx0, n, ih2);
        o11 = jac_sm(su, ly0 + 1, lx0 + 1, 66, rhs, cx, cy, gy0 + 1, gx0 + 1, n, ih2);
    }
    *reinterpret_cast<float2*>(&udst[gy0 * n + gx0]) = make_float2(o00, o01);
    *reinterpret_cast<float2*>(&udst[(gy0 + 1) * n + gx0]) = make_float2(o10, o11);
}

__global__ __launch_bounds__(256)
void pjj_kernel(const float* __restrict__ u,
                const float* __restrict__ e,
                const float* __restrict__ rhs,
                const float* __restrict__ cx,
                const float* __restrict__ cy,
                float* __restrict__ udst, int n, float ih2) {
    __shared__ float s1[20 * 68];
    __shared__ float su[18 * 66];
    int bx0 = blockIdx.x * 64, by0 = blockIdx.y * 16;
    if (blockIdx.x > 0 && blockIdx.y > 0 &&
        blockIdx.x < gridDim.x - 1 && blockIdx.y < gridDim.y - 1)
        pjj_body<true>(u, e, rhs, cx, cy, udst, n, ih2, bx0, by0, threadIdx.x, s1, su);
    else
        pjj_body<false>(u, e, rhs, cx, cy, udst, n, ih2, bx0, by0, threadIdx.x, s1, su);
}

// ===========================================================================
// l3_one: all 22 coarsest sweeps in ONE launch.
// 128 CTAs (8x16), 512 threads, owned 32x16, halo 11; coeffs in registers;
// SMEM ping-pong; software grid barrier + halo exchange at sweep 11.
// ===========================================================================
#define L3S 56

__global__ __launch_bounds__(512)
void l3_one_kernel(const float* __restrict__ r3,
                   const float* __restrict__ cx3,
                   const float* __restrict__ cy3,
                   float* __restrict__ umid,
                   float* __restrict__ uout) {
    __shared__ float ua[38 * L3S], ub[38 * L3S];
    const int tid = threadIdx.x;
    const int gx0 = blockIdx.x * 32 - 11;
    const int gy0 = blockIdx.y * 16 - 11;
    const float ih2 = 0.015625f;

    int pidx[4];
    float cae[4], caw[4], can[4], cas[4], cb[4], cu[4];
#pragma unroll
    for (int i = 0; i < 4; ++i) {
        int q = tid + 512 * i;
        pidx[i] = -1;
        cae[i] = caw[i] = can[i] = cas[i] = cb[i] = cu[i] = 0.0f;
        if (q < 36 * 52) {
            int py = q / 52 + 1, px = q % 52 + 1;
            pidx[i] = py * L3S + px;
            int gy = gy0 + py, gx = gx0 + px;
            if ((unsigned)gy < (unsigned)N3 && (unsigned)gx < (unsigned)N3) {
                int idx = gy * N3 + gx;
                float cxe = cx3[idx];
                float cxw = (gx > 0) ? cx3[idx - 1] : 0.0f;
                float cyn = cy3[idx];
                float cys = (gy > 0) ? cy3[idx - N3] : 0.0f;
                float wv = __fdividef(OMEGA_W,
                                      -((cxe + cxw) + (cyn + cys)) * ih2 - 1.0f);
                float wi = wv * ih2;
                cae[i] = wi * cxe; caw[i] = wi * cxw;
                can[i] = wi * cyn; cas[i] = wi * cys;
                cb[i] = wv * r3[idx];
            }
        }
    }

    for (int sp = tid; sp < 38 * L3S; sp += 512) { ua[sp] = 0.0f; ub[sp] = 0.0f; }
    __syncthreads();

    float* src = ua;
    float* dst = ub;
#pragma unroll 1
    for (int k = 0; k < 11; ++k) {
#pragma unroll
        for (int i = 0; i < 4; ++i) {
            int p = pidx[i];
            if (p >= 0) {
                float v = (1.0f - OMEGA_W) * cu[i] + cb[i] -
                          (cae[i] * src[p + 1] + caw[i] * src[p - 1] +
                           can[i] * src[p + L3S] + cas[i] * src[p - L3S]);
                dst[p] = v;
                cu[i] = v;
            }
        }
        __syncthreads();
        float* t = src; src = dst; dst = t;
    }

    {
        int py = 11 + (tid >> 5), px = 11 + (tid & 31);
        umid[(gy0 + py) * N3 + (gx0 + px)] = src[py * L3S + px];
    }
    __threadfence();
    __syncthreads();
    if (tid == 0) {
        unsigned ticket = atomicAdd(&g_l3_bar, 1u);
        unsigned target = (ticket / 128u + 1u) * 128u;
        while (*(volatile unsigned*)&g_l3_bar < target) __nanosleep(128);
    }
    __syncthreads();

    for (int sp = tid; sp < 38 * 54; sp += 512) {
        int py = sp / 54, px = sp % 54;
        int p = py * L3S + px;
        int gy = gy0 + py, gx = gx0 + px;
        float v = 0.0f;
        if ((unsigned)gy < (unsigned)N3 && (unsigned)gx < (unsigned)N3)
            v = umid[gy * N3 + gx];
        ua[p] = v; ub[p] = v;
    }
    __syncthreads();
#pragma unroll
    for (int i = 0; i < 4; ++i)
        if (pidx[i] >= 0) cu[i] = ua[pidx[i]];

    src = ua; dst = ub;
#pragma unroll 1
    for (int k = 0; k < 11; ++k) {
#pragma unroll
        for (int i = 0; i < 4; ++i) {
            int p = pidx[i];
            if (p >= 0) {
                float v = (1.0f - OMEGA_W) * cu[i] + cb[i] -
                          (cae[i] * src[p + 1] + caw[i] * src[p - 1] +
                           can[i] * src[p + L3S] + cas[i] * src[p - L3S]);
                dst[p] = v;
                cu[i] = v;
            }
        }
        __syncthreads();
        float* t = src; src = dst; dst = t;
    }

    {
        int py = 11 + (tid >> 5), px = 11 + (tid & 31);
        uout[(gy0 + py) * N3 + (gx0 + px)] = src[py * L3S + px];
    }
}

// ---------------------------------------------------------------------------
// Host driver: 14 launches.
// ---------------------------------------------------------------------------
extern "C" void kernel_launch(void* const* d_in, const int* in_sizes, int n_in,
                              void* d_out, int out_size) {
    const float* cx[4];
    const float* cy[4];
    const float* rhs;
    if (in_sizes[2] == in_sizes[0]) {
        for (int l = 0; l < 4; ++l) {
            cx[l] = (const float*)d_in[3 * l + 1];
            cy[l] = (const float*)d_in[3 * l + 2];
        }
        rhs = (const float*)d_in[12];
    } else {
        rhs = (const float*)d_in[0];
        for (int l = 0; l < 4; ++l) {
            cx[l] = (const float*)d_in[5 + l];
            cy[l] = (const float*)d_in[9 + l];
        }
    }

    float* uOUT = (float*)d_out;
    float *uB, *uC;
    float *u1a, *u1b, *r1;
    float *u2a, *u2b, *r2;
    float *u3a, *u3b, *r3;
    cudaGetSymbolAddress((void**)&uB, g_u0b);
    cudaGetSymbolAddress((void**)&uC, g_u0c);
    cudaGetSymbolAddress((void**)&u1a, g_u1a);
    cudaGetSymbolAddress((void**)&u1b, g_u1b);
    cudaGetSymbolAddress((void**)&r1, g_r1);
    cudaGetSymbolAddress((void**)&u2a, g_u2a);
    cudaGetSymbolAddress((void**)&u2b, g_u2b);
    cudaGetSymbolAddress((void**)&r2, g_r2);
    cudaGetSymbolAddress((void**)&u3a, g_u3a);
    cudaGetSymbolAddress((void**)&u3b, g_u3b);
    cudaGetSymbolAddress((void**)&r3, g_r3);

    const float ih2_0 = 1.0f, ih2_1 = 0.25f, ih2_2 = 0.0625f;

    dim3 t0(N0 / 64, N0 / 16);
    dim3 t1(N1 / 64, N1 / 16);
    dim3 t2(N2 / 64, N2 / 16);
    dim3 g3(8, 16);

    for (int cyc = 0; cyc < 2; ++cyc) {
        // ----- level 0: pre-smooth (2) + residual + restrict -> r1; u -> uB
        if (cyc == 0) {
            jrr0_kernel<<<t0, 256>>>(rhs, cx[0], cy[0], uB, r1, N0, ih2_0);
        } else {
            jrr2_kernel<<<t0, 256>>>(uC, rhs, cx[0], cy[0], uB, r1, N0, ih2_0);
        }

        // ----- level 1: pre (from zero) + residual + restrict -> r2
        jrr0_kernel<<<t1, 256>>>(r1, cx[1], cy[1], u1a, r2, N1, ih2_1);

        // ----- level 2: pre (from zero) + residual + restrict -> r3
        jrr0_kernel<<<t2, 256>>>(r2, cx[2], cy[2], u2a, r3, N2, ih2_2);

        // ----- level 3: all 22 sweeps in ONE launch
        l3_one_kernel<<<g3, 512>>>(r3, cx[3], cy[3], u3a, u3b);

        // ----- level 2: correct + post (2) -> u2b
        pjj_kernel<<<t2, 256>>>(u2a, u3b, r2, cx[2], cy[2], u2b, N2, ih2_2);

        // ----- level 1: correct + post (2) -> u1b
        pjj_kernel<<<t1, 256>>>(u1a, u2b, r1, cx[1], cy[1], u1b, N1, ih2_1);

        // ----- level 0: correct + post (2)
        if (cyc == 0) {
            pjj_kernel<<<t0, 256>>>(uB, u1b, rhs, cx[0], cy[0], uC, N0, ih2_0);
        } else {
            pjj_kernel<<<t0, 256>>>(uB, u1b, rhs, cx[0], cy[0], uOUT, N0, ih2_0);
        }
    }
}

// round 16
// speedup vs baseline: 1.5487x; 1.0461x over previous
#include <cuda_runtime.h>
#include <cstdint>

#define OMEGA_W 0.9f

#define N0 2048
#define N1 1024
#define N2 512
#define N3 256

// Scratch (device globals — no allocation allowed).
__device__ float g_u0b[N0 * N0];
__device__ float g_u0c[N0 * N0];
__device__ float g_u1a[N1 * N1];
__device__ float g_u1b[N1 * N1];
__device__ float g_r1[N1 * N1];
__device__ float g_u2a[N2 * N2];
__device__ float g_u2b[N2 * N2];
__device__ float g_r2[N2 * N2];
__device__ float g_u3a[N3 * N3];
__device__ float g_u3b[N3 * N3];
__device__ float g_r3[N3 * N3];

// Software grid-barrier ticket counter (monotonic; replay-safe under graphs).
__device__ unsigned int g_l3_bar = 0;

// ---------------------------------------------------------------------------
// Checked point helpers.
// ---------------------------------------------------------------------------
__device__ __forceinline__ float jac_pt(const float* __restrict__ u,
                                        const float* __restrict__ rhs,
                                        const float* __restrict__ cx,
                                        const float* __restrict__ cy,
                                        int gy, int gx, int n, float ih2) {
    int idx = gy * n + gx;
    float um = u[idx];
    float ue = (gx + 1 < n) ? u[idx + 1] : 0.0f;
    float uw = (gx > 0) ? u[idx - 1] : 0.0f;
    float uN = (gy + 1 < n) ? u[idx + n] : 0.0f;
    float uS = (gy > 0) ? u[idx - n] : 0.0f;
    float cxe = cx[idx];
    float cxw = (gx > 0) ? cx[idx - 1] : 0.0f;
    float cyn = cy[idx];
    float cys = (gy > 0) ? cy[idx - n] : 0.0f;
    float lap = (cxe * (ue - um) - cxw * (um - uw)) * ih2 +
                (cyn * (uN - um) - cys * (um - uS)) * ih2;
    float r = rhs[idx] - (lap - um);
    float diag = -((cxe + cxw) + (cyn + cys)) * ih2 - 1.0f;
    return um + __fdividef(OMEGA_W * r, diag);
}

__device__ __forceinline__ float jac_sm(const float* __restrict__ sm,
                                        int ly, int lx, int stride,
                                        const float* __restrict__ rhs,
                                        const float* __restrict__ cx,
                                        const float* __restrict__ cy,
                                        int gy, int gx, int n, float ih2) {
    int lp = ly * stride + lx;
    float um = sm[lp];
    int idx = gy * n + gx;
    float cxe = cx[idx];
    float cxw = (gx > 0) ? cx[idx - 1] : 0.0f;
    float cyn = cy[idx];
    float cys = (gy > 0) ? cy[idx - n] : 0.0f;
    float lap = (cxe * (sm[lp + 1] - um) - cxw * (um - sm[lp - 1])) * ih2 +
                (cyn * (sm[lp + stride] - um) - cys * (um - sm[lp - stride])) * ih2;
    float r = rhs[idx] - (lap - um);
    float diag = -((cxe + cxw) + (cyn + cys)) * ih2 - 1.0f;
    return um + __fdividef(OMEGA_W * r, diag);
}

__device__ __forceinline__ float resid_sm(const float* __restrict__ sm,
                                          int ly, int lx, int stride,
                                          const float* __restrict__ rhs,
                                          const float* __restrict__ cx,
                                          const float* __restrict__ cy,
                                          int gy, int gx, int n, float ih2) {
    int lp = ly * stride + lx;
    float um = sm[lp];
    int idx = gy * n + gx;
    float cxe = cx[idx];
    float cxw = (gx > 0) ? cx[idx - 1] : 0.0f;
    float cyn = cy[idx];
    float cys = (gy > 0) ? cy[idx - n] : 0.0f;
    float lap = (cxe * (sm[lp + 1] - um) - cxw * (um - sm[lp - 1])) * ih2 +
                (cyn * (sm[lp + stride] - um) - cys * (um - sm[lp - stride])) * ih2;
    return rhs[idx] - (lap - um);
}

// ---------------------------------------------------------------------------
// Unchecked (interior) point helpers — direct flat index.
// ---------------------------------------------------------------------------
__device__ __forceinline__ float jac_sm_i(const float* __restrict__ sm,
                                          int lp, int stride,
                                          const float* __restrict__ rhs,
                                          const float* __restrict__ cx,
                                          const float* __restrict__ cy,
                                          int idx, int n, float ih2) {
    float um = sm[lp];
    float cxe = cx[idx], cxw = cx[idx - 1];
    float cyn = cy[idx], cys = cy[idx - n];
    float lap = (cxe * (sm[lp + 1] - um) - cxw * (um - sm[lp - 1])) * ih2 +
                (cyn * (sm[lp + stride] - um) - cys * (um - sm[lp - stride])) * ih2;
    float r = rhs[idx] - (lap - um);
    float diag = -((cxe + cxw) + (cyn + cys)) * ih2 - 1.0f;
    return um + __fdividef(OMEGA_W * r, diag);
}

__device__ __forceinline__ float resid_sm_i(const float* __restrict__ sm,
                                            int lp, int stride,
                                            const float* __restrict__ rhs,
                                            const float* __restrict__ cx,
                                            const float* __restrict__ cy,
                                            int idx, int n, float ih2) {
    float um = sm[lp];
    float cxe = cx[idx], cxw = cx[idx - 1];
    float cyn = cy[idx], cys = cy[idx - n];
    float lap = (cxe * (sm[lp + 1] - um) - cxw * (um - sm[lp - 1])) * ih2 +
                (cyn * (sm[lp + stride] - um) - cys * (um - sm[lp - stride])) * ih2;
    return rhs[idx] - (lap - um);
}

__device__ __forceinline__ float2 ldg2(const float* __restrict__ p) {
    return *reinterpret_cast<const float2*>(p);
}

// ===========================================================================
// Shared tail (phases 2+3) for jrr0/jrr2. Phase-2 base is odd -> scalar.
// ===========================================================================
template <bool IN>
__device__ __forceinline__ void jrr_tail(const float* __restrict__ s1,
                                         float* __restrict__ su,
                                         const float* __restrict__ rhs,
                                         const float* __restrict__ cx,
                                         const float* __restrict__ cy,
                                         float* __restrict__ udst,
                                         float* __restrict__ rc,
                                         int n, float ih2,
                                         int bx0, int by0, int tid) {
    const int tx = tid & 31, ty = tid >> 5;
    const int base2 = (by0 - 1) * n + (bx0 - 1);

    for (int sp = tid; sp < 18 * 66; sp += 256) {
        int py = sp / 66;
        if (IN) {
            int idx = base2 + py * (n - 66) + sp;
            int lp = sp + 2 * py + 69;   // (py+1)*68 + (px+1)
            su[sp] = jac_sm_i(s1, lp, 68, rhs, cx, cy, idx, n, ih2);
        } else {
            int px = sp - py * 66;
            int gy = by0 + py - 1, gx = bx0 + px - 1;
            float v = 0.0f;
            if ((unsigned)gy < (unsigned)n && (unsigned)gx < (unsigned)n)
                v = jac_sm(s1, py + 1, px + 1, 68, rhs, cx, cy, gy, gx, n, ih2);
            su[sp] = v;
        }
    }
    __syncthreads();

    const int gx0 = bx0 + 2 * tx, gy0 = by0 + 2 * ty;
    const int lx0 = 2 * tx + 1, ly0 = 2 * ty + 1;

    *reinterpret_cast<float2*>(&udst[gy0 * n + gx0]) =
        make_float2(su[ly0 * 66 + lx0], su[ly0 * 66 + lx0 + 1]);
    *reinterpret_cast<float2*>(&udst[(gy0 + 1) * n + gx0]) =
        make_float2(su[(ly0 + 1) * 66 + lx0], su[(ly0 + 1) * 66 + lx0 + 1]);

    float s;
    if (IN) {
        int i00 = gy0 * n + gx0;
        int l00 = ly0 * 66 + lx0;
        s = resid_sm_i(su, l00, 66, rhs, cx, cy, i00, n, ih2) +
            resid_sm_i(su, l00 + 1, 66, rhs, cx, cy, i00 + 1, n, ih2) +
            resid_sm_i(su, l00 + 66, 66, rhs, cx, cy, i00 + n, n, ih2) +
            resid_sm_i(su, l00 + 67, 66, rhs, cx, cy, i00 + n + 1, n, ih2);
    } else {
        s = resid_sm(su, ly0, lx0, 66, rhs, cx, cy, gy0, gx0, n, ih2) +
            resid_sm(su, ly0, lx0 + 1, 66, rhs, cx, cy, gy0, gx0 + 1, n, ih2) +
            resid_sm(su, ly0 + 1, lx0, 66, rhs, cx, cy, gy0 + 1, gx0, n, ih2) +
            resid_sm(su, ly0 + 1, lx0 + 1, 66, rhs, cx, cy, gy0 + 1, gx0 + 1, n, ih2);
    }
    int nc = n >> 1;
    rc[((by0 >> 1) + ty) * nc + (bx0 >> 1) + tx] = 0.25f * s;
}

// ===========================================================================
// jrr0: u==0 start. Interior phase-1 vectorized (even base, pairs in-row).
// ===========================================================================
template <bool IN>
__device__ __forceinline__ void jrr0_body(const float* __restrict__ rhs,
                                          const float* __restrict__ cx,
                                          const float* __restrict__ cy,
                                          float* __restrict__ udst,
                                          float* __restrict__ rc,
                                          int n, float ih2,
                                          int bx0, int by0, int tid,
                                          float* s1, float* su) {
    const int base1 = (by0 - 2) * n + (bx0 - 2);
    if (IN) {
        for (int sp = 2 * tid; sp < 20 * 68; sp += 512) {
            int py = sp / 68;
            int idx = base1 + py * (n - 68) + sp;
            float2 cxe = ldg2(&cx[idx]);
            float cxw0 = cx[idx - 1];
            float2 cyn = ldg2(&cy[idx]);
            float2 cys = ldg2(&cy[idx - n]);
            float2 rh = ldg2(&rhs[idx]);
            float d0 = -((cxe.x + cxw0) + (cyn.x + cys.x)) * ih2 - 1.0f;
            float d1 = -((cxe.y + cxe.x) + (cyn.y + cys.y)) * ih2 - 1.0f;
            *reinterpret_cast<float2*>(&s1[sp]) =
                make_float2(__fdividef(OMEGA_W * rh.x, d0),
                            __fdividef(OMEGA_W * rh.y, d1));
        }
    } else {
        for (int sp = tid; sp < 20 * 68; sp += 256) {
            int py = sp / 68, px = sp - py * 68;
            int gy = by0 + py - 2, gx = bx0 + px - 2;
            float v = 0.0f;
            if ((unsigned)gy < (unsigned)n && (unsigned)gx < (unsigned)n) {
                int idx = gy * n + gx;
                float cxe = cx[idx];
                float cxw = (gx > 0) ? cx[idx - 1] : 0.0f;
                float cyn = cy[idx];
                float cys = (gy > 0) ? cy[idx - n] : 0.0f;
                float diag = -((cxe + cxw) + (cyn + cys)) * ih2 - 1.0f;
                v = __fdividef(OMEGA_W * rhs[idx], diag);
            }
            s1[sp] = v;
        }
    }
    __syncthreads();
    jrr_tail<IN>(s1, su, rhs, cx, cy, udst, rc, n, ih2, bx0, by0, tid);
}

__global__ __launch_bounds__(256)
void jrr0_kernel(const float* __restrict__ rhs,
                 const float* __restrict__ cx,
                 const float* __restrict__ cy,
                 float* __restrict__ udst,
                 float* __restrict__ rc, int n, float ih2) {
    __shared__ __align__(16) float s1[20 * 68];
    __shared__ __align__(16) float su[18 * 66];
    int bx0 = blockIdx.x * 64, by0 = blockIdx.y * 16;
    if (blockIdx.x > 0 && blockIdx.y > 0 &&
        blockIdx.x < gridDim.x - 1 && blockIdx.y < gridDim.y - 1)
        jrr0_body<true>(rhs, cx, cy, udst, rc, n, ih2, bx0, by0, threadIdx.x, s1, su);
    else
        jrr0_body<false>(rhs, cx, cy, udst, rc, n, ih2, bx0, by0, threadIdx.x, s1, su);
}

// ===========================================================================
// jrr2: nonzero u start. Interior phase-1 vectorized.
// ===========================================================================
template <bool IN>
__device__ __forceinline__ void jrr2_body(const float* __restrict__ u,
                                          const float* __restrict__ rhs,
                                          const float* __restrict__ cx,
                                          const float* __restrict__ cy,
                                          float* __restrict__ udst,
                                          float* __restrict__ rc,
                                          int n, float ih2,
                                          int bx0, int by0, int tid,
                                          float* s1, float* su) {
    const int base1 = (by0 - 2) * n + (bx0 - 2);
    if (IN) {
        for (int sp = 2 * tid; sp < 20 * 68; sp += 512) {
            int py = sp / 68;
            int idx = base1 + py * (n - 68) + sp;
            float2 um = ldg2(&u[idx]);
            float uw0 = u[idx - 1];
            float ue1 = u[idx + 2];
            float2 uN = ldg2(&u[idx + n]);
            float2 uS = ldg2(&u[idx - n]);
            float2 cxe = ldg2(&cx[idx]);
            float cxw0 = cx[idx - 1];
            float2 cyn = ldg2(&cy[idx]);
            float2 cys = ldg2(&cy[idx - n]);
            float2 rh = ldg2(&rhs[idx]);

            float lap0 = (cxe.x * (um.y - um.x) - cxw0 * (um.x - uw0)) * ih2 +
                         (cyn.x * (uN.x - um.x) - cys.x * (um.x - uS.x)) * ih2;
            float r0 = rh.x - (lap0 - um.x);
            float d0 = -((cxe.x + cxw0) + (cyn.x + cys.x)) * ih2 - 1.0f;

            float lap1 = (cxe.y * (ue1 - um.y) - cxe.x * (um.y - um.x)) * ih2 +
                         (cyn.y * (uN.y - um.y) - cys.y * (um.y - uS.y)) * ih2;
            float r1 = rh.y - (lap1 - um.y);
            float d1 = -((cxe.y + cxe.x) + (cyn.y + cys.y)) * ih2 - 1.0f;

            *reinterpret_cast<float2*>(&s1[sp]) =
                make_float2(um.x + __fdividef(OMEGA_W * r0, d0),
                            um.y + __fdividef(OMEGA_W * r1, d1));
        }
    } else {
        for (int sp = tid; sp < 20 * 68; sp += 256) {
            int py = sp / 68, px = sp - py * 68;
            int gy = by0 + py - 2, gx = bx0 + px - 2;
            float v = 0.0f;
            if ((unsigned)gy < (unsigned)n && (unsigned)gx < (unsigned)n)
                v = jac_pt(u, rhs, cx, cy, gy, gx, n, ih2);
            s1[sp] = v;
        }
    }
    __syncthreads();
    jrr_tail<IN>(s1, su, rhs, cx, cy, udst, rc, n, ih2, bx0, by0, tid);
}

__global__ __launch_bounds__(256)
void jrr2_kernel(const float* __restrict__ u,
                 const float* __restrict__ rhs,
                 const float* __restrict__ cx,
                 const float* __restrict__ cy,
                 float* __restrict__ udst,
                 float* __restrict__ rc, int n, float ih2) {
    __shared__ __align__(16) float s1[20 * 68];
    __shared__ __align__(16) float su[18 * 66];
    int bx0 = blockIdx.x * 64, by0 = blockIdx.y * 16;
    if (blockIdx.x > 0 && blockIdx.y > 0 &&
        blockIdx.x < gridDim.x - 1 && blockIdx.y < gridDim.y - 1)
        jrr2_body<true>(u, rhs, cx, cy, udst, rc, n, ih2, bx0, by0, threadIdx.x, s1, su);
    else
        jrr2_body<false>(u, rhs, cx, cy, udst, rc, n, ih2, bx0, by0, threadIdx.x, s1, su);
}

// ===========================================================================
// pjj: {u += prolong(e)} + two Jacobi sweeps. Interior phase-0 vectorized
// (pairs share ic: even px -> si=-1, odd px -> si=+1, same ic).
// ===========================================================================
template <bool IN>
__device__ __forceinline__ void pjj_body(const float* __restrict__ u,
                                         const float* __restrict__ e,
                                         const float* __restrict__ rhs,
                                         const float* __restrict__ cx,
                                         const float* __restrict__ cy,
                                         float* __restrict__ udst,
                                         int n, float ih2,
                                         int bx0, int by0, int tid,
                                         float* s1, float* su) {
    const int tx = tid & 31, ty = tid >> 5;
    const int ncc = n >> 1;
    const int base1 = (by0 - 2) * n + (bx0 - 2);
    const int jb = (by0 - 2) >> 1;
    const int ib = (bx0 - 2) >> 1;

    if (IN) {
        for (int sp = 2 * tid; sp < 20 * 68; sp += 512) {
            int py = sp / 68, px = sp - py * 68;   // px even
            int idx = base1 + py * (n - 68) + sp;
            int jc = jb + (py >> 1);
            int sj = (py & 1) ? 1 : -1;
            int ic = ib + (px >> 1);
            const float* er = e + jc * ncc;
            const float* erj = e + (jc + sj) * ncc;
            float e0 = er[ic], em = er[ic - 1], ep = er[ic + 1];
            float f0 = erj[ic], fm = erj[ic - 1], fp = erj[ic + 1];
            float2 uu = ldg2(&u[idx]);
            float w0 = 9.0f * e0 + 3.0f * em + 3.0f * f0 + fm;
            float w1 = 9.0f * e0 + 3.0f * ep + 3.0f * f0 + fp;
            *reinterpret_cast<float2*>(&s1[sp]) =
                make_float2(uu.x + w0 * 0.0625f, uu.y + w1 * 0.0625f);
        }
    } else {
        for (int sp = tid; sp < 20 * 68; sp += 256) {
            int py = sp / 68, px = sp - py * 68;
            int gy = by0 + py - 2, gx = bx0 + px - 2;
            float v = 0.0f;
            if ((unsigned)gy < (unsigned)n && (unsigned)gx < (unsigned)n) {
                int jc = gy >> 1, dj = gy & 1;
                int ic = gx >> 1, di = gx & 1;
                int sj = dj ? 1 : -1;
                int si = di ? 1 : -1;
                bool bi = ((unsigned)(ic + si) < (unsigned)ncc);
                bool bj = ((unsigned)(jc + sj) < (unsigned)ncc);
                float vc = e[jc * ncc + ic];
                float vsi = bi ? e[jc * ncc + ic + si] : 0.0f;
                float vsj = bj ? e[(jc + sj) * ncc + ic] : 0.0f;
                float vd = (bi && bj) ? e[(jc + sj) * ncc + ic + si] : 0.0f;
                float den = 9.0f + 3.0f * (bi ? 1.0f : 0.0f) +
                            3.0f * (bj ? 1.0f : 0.0f) + ((bi && bj) ? 1.0f : 0.0f);
                v = u[gy * n + gx] +
                    __fdividef(9.0f * vc + 3.0f * vsi + 3.0f * vsj + vd, den);
            }
            s1[sp] = v;
        }
    }
    __syncthreads();

    const int base2 = (by0 - 1) * n + (bx0 - 1);
    for (int sp = tid; sp < 18 * 66; sp += 256) {
        int py = sp / 66;
        if (IN) {
            int idx = base2 + py * (n - 66) + sp;
            int lp = sp + 2 * py + 69;
            su[sp] = jac_sm_i(s1, lp, 68, rhs, cx, cy, idx, n, ih2);
        } else {
            int px = sp - py * 66;
            int gy = by0 + py - 1, gx = bx0 + px - 1;
            float v = 0.0f;
            if ((unsigned)gy < (unsigned)n && (unsigned)gx < (unsigned)n)
                v = jac_sm(s1, py + 1, px + 1, 68, rhs, cx, cy, gy, gx, n, ih2);
            su[sp] = v;
        }
    }
    __syncthreads();

    const int gx0 = bx0 + 2 * tx, gy0 = by0 + 2 * ty;
    const int lx0 = 2 * tx + 1, ly0 = 2 * ty + 1;
    float o00, o01, o10, o11;
    if (IN) {
        int i00 = gy0 * n + gx0;
        int l00 = ly0 * 66 + lx0;
        o00 = jac_sm_i(su, l00, 66, rhs, cx, cy, i00, n, ih2);
        o01 = jac_sm_i(su, l00 + 1, 66, rhs, cx, cy, i00 + 1, n, ih2);
        o10 = jac_sm_i(su, l00 + 66, 66, rhs, cx, cy, i00 + n, n, ih2);
        o11 = jac_sm_i(su, l00 + 67, 66, rhs, cx, cy, i00 + n + 1, n, ih2);
    } else {
        o00 = jac_sm(su, ly0, lx0, 66, rhs, cx, cy, gy0, gx0, n, ih2);
        o01 = jac_sm(su, ly0, lx0 + 1, 66, rhs, cx, cy, gy0, gx0 + 1, n, ih2);
        o10 = jac_sm(su, ly0 + 1, lx0, 66, rhs, cx, cy, gy0 + 1, gx0, n, ih2);
        o11 = jac_sm(su, ly0 + 1, lx0 + 1, 66, rhs, cx, cy, gy0 + 1, gx0 + 1, n, ih2);
    }
    *reinterpret_cast<float2*>(&udst[gy0 * n + gx0]) = make_float2(o00, o01);
    *reinterpret_cast<float2*>(&udst[(gy0 + 1) * n + gx0]) = make_float2(o10, o11);
}

__global__ __launch_bounds__(256)
void pjj_kernel(const float* __restrict__ u,
                const float* __restrict__ e,
                const float* __restrict__ rhs,
                const float* __restrict__ cx,
                const float* __restrict__ cy,
                float* __restrict__ udst, int n, float ih2) {
    __shared__ __align__(16) float s1[20 * 68];
    __shared__ __align__(16) float su[18 * 66];
    int bx0 = blockIdx.x * 64, by0 = blockIdx.y * 16;
    if (blockIdx.x > 0 && blockIdx.y > 0 &&
        blockIdx.x < gridDim.x - 1 && blockIdx.y < gridDim.y - 1)
        pjj_body<true>(u, e, rhs, cx, cy, udst, n, ih2, bx0, by0, threadIdx.x, s1, su);
    else
        pjj_body<false>(u, e, rhs, cx, cy, udst, n, ih2, bx0, by0, threadIdx.x, s1, su);
}

// ===========================================================================
// l3_one (verified ~15us): all 22 coarsest sweeps in ONE launch.
// ===========================================================================
#define L3S 56

__global__ __launch_bounds__(512)
void l3_one_kernel(const float* __restrict__ r3,
                   const float* __restrict__ cx3,
                   const float* __restrict__ cy3,
                   float* __restrict__ umid,
                   float* __restrict__ uout) {
    __shared__ float ua[38 * L3S], ub[38 * L3S];
    const int tid = threadIdx.x;
    const int gx0 = blockIdx.x * 32 - 11;
    const int gy0 = blockIdx.y * 16 - 11;
    const float ih2 = 0.015625f;

    int pidx[4];
    float cae[4], caw[4], can[4], cas[4], cb[4], cu[4];
#pragma unroll
    for (int i = 0; i < 4; ++i) {
        int q = tid + 512 * i;
        pidx[i] = -1;
        cae[i] = caw[i] = can[i] = cas[i] = cb[i] = cu[i] = 0.0f;
        if (q < 36 * 52) {
            int py = q / 52 + 1, px = q % 52 + 1;
            pidx[i] = py * L3S + px;
            int gy = gy0 + py, gx = gx0 + px;
            if ((unsigned)gy < (unsigned)N3 && (unsigned)gx < (unsigned)N3) {
                int idx = gy * N3 + gx;
                float cxe = cx3[idx];
                float cxw = (gx > 0) ? cx3[idx - 1] : 0.0f;
                float cyn = cy3[idx];
                float cys = (gy > 0) ? cy3[idx - N3] : 0.0f;
                float wv = __fdividef(OMEGA_W,
                                      -((cxe + cxw) + (cyn + cys)) * ih2 - 1.0f);
                float wi = wv * ih2;
                cae[i] = wi * cxe; caw[i] = wi * cxw;
                can[i] = wi * cyn; cas[i] = wi * cys;
                cb[i] = wv * r3[idx];
            }
        }
    }

    for (int sp = tid; sp < 38 * L3S; sp += 512) { ua[sp] = 0.0f; ub[sp] = 0.0f; }
    __syncthreads();

    float* src = ua;
    float* dst = ub;
#pragma unroll 1
    for (int k = 0; k < 11; ++k) {
#pragma unroll
        for (int i = 0; i < 4; ++i) {
            int p = pidx[i];
            if (p >= 0) {
                float v = (1.0f - OMEGA_W) * cu[i] + cb[i] -
                          (cae[i] * src[p + 1] + caw[i] * src[p - 1] +
                           can[i] * src[p + L3S] + cas[i] * src[p - L3S]);
                dst[p] = v;
                cu[i] = v;
            }
        }
        __syncthreads();
        float* t = src; src = dst; dst = t;
    }

    {
        int py = 11 + (tid >> 5), px = 11 + (tid & 31);
        umid[(gy0 + py) * N3 + (gx0 + px)] = src[py * L3S + px];
    }
    __threadfence();
    __syncthreads();
    if (tid == 0) {
        unsigned ticket = atomicAdd(&g_l3_bar, 1u);
        unsigned target = (ticket / 128u + 1u) * 128u;
        while (*(volatile unsigned*)&g_l3_bar < target) __nanosleep(128);
    }
    __syncthreads();

    for (int sp = tid; sp < 38 * 54; sp += 512) {
        int py = sp / 54, px = sp % 54;
        int p = py * L3S + px;
        int gy = gy0 + py, gx = gx0 + px;
        float v = 0.0f;
        if ((unsigned)gy < (unsigned)N3 && (unsigned)gx < (unsigned)N3)
            v = umid[gy * N3 + gx];
        ua[p] = v; ub[p] = v;
    }
    __syncthreads();
#pragma unroll
    for (int i = 0; i < 4; ++i)
        if (pidx[i] >= 0) cu[i] = ua[pidx[i]];

    src = ua; dst = ub;
#pragma unroll 1
    for (int k = 0; k < 11; ++k) {
#pragma unroll
        for (int i = 0; i < 4; ++i) {
            int p = pidx[i];
            if (p >= 0) {
                float v = (1.0f - OMEGA_W) * cu[i] + cb[i] -
                          (cae[i] * src[p + 1] + caw[i] * src[p - 1] +
                           can[i] * src[p + L3S] + cas[i] * src[p - L3S]);
                dst[p] = v;
                cu[i] = v;
            }
        }
        __syncthreads();
        float* t = src; src = dst; dst = t;
    }

    {
        int py = 11 + (tid >> 5), px = 11 + (tid & 31);
        uout[(gy0 + py) * N3 + (gx0 + px)] = src[py * L3S + px];
    }
}

// ---------------------------------------------------------------------------
// Host driver: 14 launches.
// ---------------------------------------------------------------------------
extern "C" void kernel_launch(void* const* d_in, const int* in_sizes, int n_in,
                              void* d_out, int out_size) {
    const float* cx[4];
    const float* cy[4];
    const float* rhs;
    if (in_sizes[2] == in_sizes[0]) {
        for (int l = 0; l < 4; ++l) {
            cx[l] = (const float*)d_in[3 * l + 1];
            cy[l] = (const float*)d_in[3 * l + 2];
        }
        rhs = (const float*)d_in[12];
    } else {
        rhs = (const float*)d_in[0];
        for (int l = 0; l < 4; ++l) {
            cx[l] = (const float*)d_in[5 + l];
            cy[l] = (const float*)d_in[9 + l];
        }
    }

    float* uOUT = (float*)d_out;
    float *uB, *uC;
    float *u1a, *u1b, *r1;
    float *u2a, *u2b, *r2;
    float *u3a, *u3b, *r3;
    cudaGetSymbolAddress((void**)&uB, g_u0b);
    cudaGetSymbolAddress((void**)&uC, g_u0c);
    cudaGetSymbolAddress((void**)&u1a, g_u1a);
    cudaGetSymbolAddress((void**)&u1b, g_u1b);
    cudaGetSymbolAddress((void**)&r1, g_r1);
    cudaGetSymbolAddress((void**)&u2a, g_u2a);
    cudaGetSymbolAddress((void**)&u2b, g_u2b);
    cudaGetSymbolAddress((void**)&r2, g_r2);
    cudaGetSymbolAddress((void**)&u3a, g_u3a);
    cudaGetSymbolAddress((void**)&u3b, g_u3b);
    cudaGetSymbolAddress((void**)&r3, g_r3);

    const float ih2_0 = 1.0f, ih2_1 = 0.25f, ih2_2 = 0.0625f;

    dim3 t0(N0 / 64, N0 / 16);
    dim3 t1(N1 / 64, N1 / 16);
    dim3 t2(N2 / 64, N2 / 16);
    dim3 g3(8, 16);

    for (int cyc = 0; cyc < 2; ++cyc) {
        // ----- level 0: pre-smooth (2) + residual + restrict -> r1; u -> uB
        if (cyc == 0) {
            jrr0_kernel<<<t0, 256>>>(rhs, cx[0], cy[0], uB, r1, N0, ih2_0);
        } else {
            jrr2_kernel<<<t0, 256>>>(uC, rhs, cx[0], cy[0], uB, r1, N0, ih2_0);
        }

        // ----- level 1: pre (from zero) + residual + restrict -> r2
        jrr0_kernel<<<t1, 256>>>(r1, cx[1], cy[1], u1a, r2, N1, ih2_1);

        // ----- level 2: pre (from zero) + residual + restrict -> r3
        jrr0_kernel<<<t2, 256>>>(r2, cx[2], cy[2], u2a, r3, N2, ih2_2);

        // ----- level 3: all 22 sweeps in ONE launch
        l3_one_kernel<<<g3, 512>>>(r3, cx[3], cy[3], u3a, u3b);

        // ----- level 2: correct + post (2) -> u2b
        pjj_kernel<<<t2, 256>>>(u2a, u3b, r2, cx[2], cy[2], u2b, N2, ih2_2);

        // ----- level 1: correct + post (2) -> u1b
        pjj_kernel<<<t1, 256>>>(u1a, u2b, r1, cx[1], cy[1], u1b, N1, ih2_1);

        // ----- level 0: correct + post (2)
        if (cyc == 0) {
            pjj_kernel<<<t0, 256>>>(uB, u1b, rhs, cx[0], cy[0], uC, N0, ih2_0);
        } else {
            pjj_kernel<<<t0, 256>>>(uB, u1b, rhs, cx[0], cy[0], uOUT, N0, ih2_0);
        }
    }
}